// round 15
// baseline (speedup 1.0000x reference)
#include <cuda_runtime.h>
#include <cuda_fp16.h>
#include <cstdint>

#define BB 4
#define NN 2048
#define DD 1024
#define MTOT (BB * NN)  // 8192

// fp16 scratch (allocation-free rule: __device__ globals)
static __device__ __align__(256) half g_xh[MTOT * DD];
static __device__ __align__(256) half g_wqh[DD * DD];
static __device__ __align__(256) half g_wkh[DD * DD];
static __device__ __align__(256) half g_wvh[DD * DD];
static __device__ __align__(256) half g_woh[DD * DD];
static __device__ __align__(256) half g_q[MTOT * DD];
static __device__ __align__(256) half g_k[MTOT * DD];
static __device__ __align__(256) half g_v[MTOT * DD];
static __device__ __align__(256) half g_a[MTOT * DD];

// ---------------------------------------------------------------------------
__device__ __forceinline__ uint32_t h2u(half2 h) {
    return *reinterpret_cast<uint32_t*>(&h);
}

__device__ __forceinline__ float ex2(float x) {
    float r;
    asm("ex2.approx.f32 %0, %1;" : "=f"(r) : "f"(x));
    return r;
}

__device__ __forceinline__ void mma_f16(float d[4], const uint32_t a[4],
                                        const uint32_t b[2]) {
    asm volatile(
        "mma.sync.aligned.m16n8k16.row.col.f32.f16.f16.f32 "
        "{%0,%1,%2,%3}, {%4,%5,%6,%7}, {%8,%9}, {%0,%1,%2,%3};"
        : "+f"(d[0]), "+f"(d[1]), "+f"(d[2]), "+f"(d[3])
        : "r"(a[0]), "r"(a[1]), "r"(a[2]), "r"(a[3]), "r"(b[0]), "r"(b[1]));
}

__device__ __forceinline__ void ldsm4(uint32_t& m0, uint32_t& m1, uint32_t& m2,
                                      uint32_t& m3, const half* p) {
    uint32_t sa = (uint32_t)__cvta_generic_to_shared(p);
    asm volatile(
        "ldmatrix.sync.aligned.m8n8.x4.shared.b16 {%0,%1,%2,%3}, [%4];"
        : "=r"(m0), "=r"(m1), "=r"(m2), "=r"(m3) : "r"(sa));
}

__device__ __forceinline__ void ldsm4t(uint32_t& m0, uint32_t& m1, uint32_t& m2,
                                       uint32_t& m3, const half* p) {
    uint32_t sa = (uint32_t)__cvta_generic_to_shared(p);
    asm volatile(
        "ldmatrix.sync.aligned.m8n8.x4.trans.shared.b16 {%0,%1,%2,%3}, [%4];"
        : "=r"(m0), "=r"(m1), "=r"(m2), "=r"(m3) : "r"(sa));
}

__device__ __forceinline__ void cp16(void* smem, const void* g) {
    uint32_t s = (uint32_t)__cvta_generic_to_shared(smem);
    asm volatile("cp.async.ca.shared.global [%0], [%1], 16;" :: "r"(s), "l"(g));
}

// ---------------------------------------------------------------------------
// fused convert: y=0 -> x (scale 1), y=1..4 -> Wq(qscale)/Wk/Wv/Wo
// unroll x4 with upfront loads for MLP
// ---------------------------------------------------------------------------
__global__ void conv_all(const float* __restrict__ x,
                         const float* __restrict__ Wq,
                         const float* __restrict__ Wk,
                         const float* __restrict__ Wv,
                         const float* __restrict__ Wo,
                         half* ox, half* oq, half* ok, half* ov, half* oo,
                         float qscale)
{
    const int ysel = blockIdx.y;
    const float* in = (ysel == 0) ? x : (ysel == 1) ? Wq : (ysel == 2) ? Wk
                                      : (ysel == 3) ? Wv : Wo;
    half* out = (ysel == 0) ? ox : (ysel == 1) ? oq : (ysel == 2) ? ok
                                 : (ysel == 3) ? ov : oo;
    const float s = (ysel == 1) ? qscale : 1.0f;
    const int n4 = (ysel == 0) ? (MTOT * DD / 4) : (DD * DD / 4);
    const int stride = gridDim.x * blockDim.x;
    int i = blockIdx.x * blockDim.x + threadIdx.x;
    for (; i + 3 * stride < n4; i += 4 * stride) {
        float4 f0 = ((const float4*)in)[i];
        float4 f1 = ((const float4*)in)[i + stride];
        float4 f2 = ((const float4*)in)[i + 2 * stride];
        float4 f3 = ((const float4*)in)[i + 3 * stride];
        ((half2*)out)[2 * i]     = __floats2half2_rn(f0.x * s, f0.y * s);
        ((half2*)out)[2 * i + 1] = __floats2half2_rn(f0.z * s, f0.w * s);
        ((half2*)out)[2 * (i + stride)]     = __floats2half2_rn(f1.x * s, f1.y * s);
        ((half2*)out)[2 * (i + stride) + 1] = __floats2half2_rn(f1.z * s, f1.w * s);
        ((half2*)out)[2 * (i + 2 * stride)]     = __floats2half2_rn(f2.x * s, f2.y * s);
        ((half2*)out)[2 * (i + 2 * stride) + 1] = __floats2half2_rn(f2.z * s, f2.w * s);
        ((half2*)out)[2 * (i + 3 * stride)]     = __floats2half2_rn(f3.x * s, f3.y * s);
        ((half2*)out)[2 * (i + 3 * stride) + 1] = __floats2half2_rn(f3.z * s, f3.w * s);
    }
    for (; i < n4; i += stride) {
        float4 f = ((const float4*)in)[i];
        ((half2*)out)[2 * i]     = __floats2half2_rn(f.x * s, f.y * s);
        ((half2*)out)[2 * i + 1] = __floats2half2_rn(f.z * s, f.w * s);
    }
}

// ---------------------------------------------------------------------------
// fp16 GEMM v3: block 128x128, BK=64, 128 threads (4 warps, 2m x 2n),
// warp tile 64x64, 3-stage cp.async, ONE barrier per 64-k chunk.
// smem: 3*(128*72 + 64*136)*2 = 107520 B -> 2 blocks/SM.
// ---------------------------------------------------------------------------
#define GAH2 72
#define GBH 136
#define GSTG (128 * GAH2 + 64 * GBH)   // 17920 halves per stage

template <bool HOUT>
__global__ __launch_bounds__(128, 2) void gemm_f16(
    const half* __restrict__ A,
    const half* __restrict__ W0, const half* __restrict__ W1,
    const half* __restrict__ W2,
    void* __restrict__ C0, void* __restrict__ C1, void* __restrict__ C2,
    int M, int N, int K)
{
    const half* Bm = (blockIdx.z == 0) ? W0 : (blockIdx.z == 1) ? W1 : W2;
    void* Cv = (blockIdx.z == 0) ? C0 : (blockIdx.z == 1) ? C1 : C2;

    extern __shared__ half gsm[];

    const int tid = threadIdx.x;
    const int lane = tid & 31;
    const int wid = tid >> 5;          // 0..3
    const int wm = (wid & 1) * 64;
    const int wn = (wid >> 1) * 64;
    const int g  = lane >> 2;
    const int c4 = lane & 3;
    const int rowBase = blockIdx.y * 128;
    const int colBase = blockIdx.x * 128;

    const int arow = (lane & 7) + ((lane >> 3) & 1) * 8;
    const int acol = (lane >> 4) * 8;

    float acc[4][8][4] = {};

    auto load_stage = [&](int kt, int stg) {
        half* Asb = gsm + stg * GSTG;
        half* Bsb = Asb + 128 * GAH2;
#pragma unroll
        for (int j = 0; j < 8; j++) {
            int ch = tid + 128 * j;        // 1024 chunks of 8 halves (A)
            int r = ch >> 3, c = (ch & 7) * 8;
            cp16(&Asb[r * GAH2 + c], A + (size_t)(rowBase + r) * K + kt + c);
        }
#pragma unroll
        for (int j = 0; j < 8; j++) {
            int ch = tid + 128 * j;        // 1024 chunks of 8 halves (B)
            int kr = ch >> 4, c = (ch & 15) * 8;
            cp16(&Bsb[kr * GBH + c],
                 Bm + (size_t)(kt + kr) * N + colBase + c);
        }
        asm volatile("cp.async.commit_group;" ::: "memory");
    };

    load_stage(0, 0);
    load_stage(64, 1);

    const int T = K / 64;   // 16
    for (int t = 0; t < T; t++) {
        if (t + 1 < T)
            asm volatile("cp.async.wait_group 1;" ::: "memory");
        else
            asm volatile("cp.async.wait_group 0;" ::: "memory");
        __syncthreads();   // stage t ready; all warps done with stage (t-1)

        int stg = t % 3;
        const half* Asb = gsm + stg * GSTG;
        const half* Bsb = Asb + 128 * GAH2;

#pragma unroll
        for (int ks = 0; ks < 4; ks++) {
            uint32_t a[4][4], b[8][2];
#pragma unroll
            for (int mt = 0; mt < 4; mt++)
                ldsm4(a[mt][0], a[mt][1], a[mt][2], a[mt][3],
                      Asb + (wm + mt * 16 + arow) * GAH2 + ks * 16 + acol);
#pragma unroll
            for (int ntp = 0; ntp < 4; ntp++)
                ldsm4t(b[2 * ntp][0], b[2 * ntp][1],
                       b[2 * ntp + 1][0], b[2 * ntp + 1][1],
                       Bsb + (ks * 16 + arow) * GBH + wn + ntp * 16 + acol);
#pragma unroll
            for (int mt = 0; mt < 4; mt++)
#pragma unroll
                for (int nt = 0; nt < 8; nt++)
                    mma_f16(acc[mt][nt], a[mt], b[nt]);
        }

        if (t + 2 < T)
            load_stage((t + 2) * 64, (t + 2) % 3);
    }

#pragma unroll
    for (int mt = 0; mt < 4; mt++) {
        int r0 = rowBase + wm + mt * 16 + g;
#pragma unroll
        for (int nt = 0; nt < 8; nt++) {
            int cc = colBase + wn + nt * 8 + 2 * c4;
            if (HOUT) {
                half* C = (half*)Cv;
                *(half2*)(C + (size_t)r0 * N + cc) =
                    __floats2half2_rn(acc[mt][nt][0], acc[mt][nt][1]);
                *(half2*)(C + (size_t)(r0 + 8) * N + cc) =
                    __floats2half2_rn(acc[mt][nt][2], acc[mt][nt][3]);
            } else {
                float* C = (float*)Cv;
                *(float2*)(C + (size_t)r0 * N + cc) =
                    make_float2(acc[mt][nt][0], acc[mt][nt][1]);
                *(float2*)(C + (size_t)(r0 + 8) * N + cc) =
                    make_float2(acc[mt][nt][2], acc[mt][nt][3]);
            }
        }
    }
}

// ---------------------------------------------------------------------------
// fp16 flash attention (unchanged from R14 passing version).
// 128 threads, 4 warps x 32 q-rows, 2 blocks/SM, base-2 softmax.
// ---------------------------------------------------------------------------
#define QP 136
#define KVSZ (64 * QP)

__global__ __launch_bounds__(128, 2) void attn_f16(
    const half* __restrict__ Q, const half* __restrict__ K,
    const half* __restrict__ V, half* __restrict__ O)
{
    extern __shared__ half smh[];
    half* Qs = smh;                    // 128*136
    half* Ks = Qs + 128 * QP;          // [2][64*136]
    half* Vs = Ks + 2 * KVSZ;          // [2][64*136]

    const int tid = threadIdx.x;
    const int lane = tid & 31;
    const int wid = tid >> 5;          // 0..3 -> q rows 32*wid..
    const int g  = lane >> 2;
    const int c4 = lane & 3;
    const int qt = blockIdx.x;
    const int bh = blockIdx.y;
    const int b = bh >> 3;
    const int h = bh & 7;

    const int rb0 = wid * 32;
    const int rb1 = wid * 32 + 16;
    const int qa = rb0 + g;
    const int qb = qa + 8;
    const int qc = rb1 + g;
    const int qd = qc + 8;

    const int arow = (lane & 7) + ((lane >> 3) & 1) * 8;
    const int acol = (lane >> 4) * 8;
    const int brow = (lane & 7) + ((lane >> 4) & 1) * 8;
    const int bcol = ((lane >> 3) & 1) * 8;

    const size_t headOff = (size_t)b * NN * DD + (size_t)h * 128;
    const half* Qp = Q + headOff + (size_t)(qt * 128) * DD;
    const half* Kp = K + headOff;
    const half* Vp = V + headOff;

    auto load_kv = [&](int kt, int bufi) {
#pragma unroll
        for (int j = 0; j < 8; j++) {
            int ch = tid + 128 * j;
            int r = ch >> 4, c = (ch & 15) * 8;
            const size_t go = (size_t)(kt * 64 + r) * DD + c;
            cp16(&Ks[bufi * KVSZ + r * QP + c], Kp + go);
            cp16(&Vs[bufi * KVSZ + r * QP + c], Vp + go);
        }
    };

#pragma unroll
    for (int j = 0; j < 16; j++) {
        int ch = tid + 128 * j;
        int r = ch >> 4, c = (ch & 15) * 8;
        cp16(&Qs[r * QP + c], Qp + (size_t)r * DD + c);
    }
    load_kv(0, 0);
    asm volatile("cp.async.commit_group;" ::: "memory");

    float o[2][16][4] = {};
    float m_a = -1e30f, m_b = -1e30f, m_c = -1e30f, m_d = -1e30f;
    float l_a = 0.f, l_b = 0.f, l_c = 0.f, l_d = 0.f;

    for (int kt = 0; kt < 32; kt++) {
        asm volatile("cp.async.wait_group 0;" ::: "memory");
        __syncthreads();
        if (kt + 1 < 32) {
            load_kv(kt + 1, (kt + 1) & 1);
            asm volatile("cp.async.commit_group;" ::: "memory");
        }
        const half* Kb = Ks + (kt & 1) * KVSZ;
        const half* Vb = Vs + (kt & 1) * KVSZ;

        // --- S = Q K^T (base-2 logits) ---
        float s[2][8][4] = {};
#pragma unroll
        for (int ks = 0; ks < 8; ks++) {
            uint32_t a0[4], a1[4];
            ldsm4(a0[0], a0[1], a0[2], a0[3],
                  Qs + (rb0 + arow) * QP + ks * 16 + acol);
            ldsm4(a1[0], a1[1], a1[2], a1[3],
                  Qs + (rb1 + arow) * QP + ks * 16 + acol);
#pragma unroll
            for (int ntp = 0; ntp < 4; ntp++) {
                uint32_t bf0[2], bf1[2];
                ldsm4(bf0[0], bf0[1], bf1[0], bf1[1],
                      Kb + (ntp * 16 + brow) * QP + ks * 16 + bcol);
                mma_f16(s[0][2 * ntp], a0, bf0);
                mma_f16(s[0][2 * ntp + 1], a0, bf1);
                mma_f16(s[1][2 * ntp], a1, bf0);
                mma_f16(s[1][2 * ntp + 1], a1, bf1);
            }
        }

        // --- warp-local softmax (base 2) ---
        float pa = -1e30f, pb = -1e30f, pc = -1e30f, pd = -1e30f;
#pragma unroll
        for (int nt = 0; nt < 8; nt++) {
            pa = fmaxf(pa, fmaxf(s[0][nt][0], s[0][nt][1]));
            pb = fmaxf(pb, fmaxf(s[0][nt][2], s[0][nt][3]));
            pc = fmaxf(pc, fmaxf(s[1][nt][0], s[1][nt][1]));
            pd = fmaxf(pd, fmaxf(s[1][nt][2], s[1][nt][3]));
        }
        pa = fmaxf(pa, __shfl_xor_sync(0xffffffffu, pa, 1));
        pa = fmaxf(pa, __shfl_xor_sync(0xffffffffu, pa, 2));
        pb = fmaxf(pb, __shfl_xor_sync(0xffffffffu, pb, 1));
        pb = fmaxf(pb, __shfl_xor_sync(0xffffffffu, pb, 2));
        pc = fmaxf(pc, __shfl_xor_sync(0xffffffffu, pc, 1));
        pc = fmaxf(pc, __shfl_xor_sync(0xffffffffu, pc, 2));
        pd = fmaxf(pd, __shfl_xor_sync(0xffffffffu, pd, 1));
        pd = fmaxf(pd, __shfl_xor_sync(0xffffffffu, pd, 2));
        float na = fmaxf(m_a, pa), nb = fmaxf(m_b, pb);
        float nc = fmaxf(m_c, pc), nd = fmaxf(m_d, pd);
        float aa = ex2(m_a - na), ab = ex2(m_b - nb);
        float ac = ex2(m_c - nc), ad = ex2(m_d - nd);
        m_a = na; m_b = nb; m_c = nc; m_d = nd;

        uint32_t aP[2][4][4];
        float sa = 0.f, sb = 0.f, sc = 0.f, sd = 0.f;
#pragma unroll
        for (int nt = 0; nt < 8; nt++) {
            int kc = nt >> 1;
            int sl = (nt & 1) * 2;
            {
                float p0 = ex2(s[0][nt][0] - na);
                float p1 = ex2(s[0][nt][1] - na);
                float p2 = ex2(s[0][nt][2] - nb);
                float p3 = ex2(s[0][nt][3] - nb);
                sa += p0 + p1;
                sb += p2 + p3;
                aP[0][kc][sl]     = h2u(__floats2half2_rn(p0, p1));
                aP[0][kc][sl + 1] = h2u(__floats2half2_rn(p2, p3));
            }
            {
                float p0 = ex2(s[1][nt][0] - nc);
                float p1 = ex2(s[1][nt][1] - nc);
                float p2 = ex2(s[1][nt][2] - nd);
                float p3 = ex2(s[1][nt][3] - nd);
                sc += p0 + p1;
                sd += p2 + p3;
                aP[1][kc][sl]     = h2u(__floats2half2_rn(p0, p1));
                aP[1][kc][sl + 1] = h2u(__floats2half2_rn(p2, p3));
            }
        }
        sa += __shfl_xor_sync(0xffffffffu, sa, 1);
        sa += __shfl_xor_sync(0xffffffffu, sa, 2);
        sb += __shfl_xor_sync(0xffffffffu, sb, 1);
        sb += __shfl_xor_sync(0xffffffffu, sb, 2);
        sc += __shfl_xor_sync(0xffffffffu, sc, 1);
        sc += __shfl_xor_sync(0xffffffffu, sc, 2);
        sd += __shfl_xor_sync(0xffffffffu, sd, 1);
        sd += __shfl_xor_sync(0xffffffffu, sd, 2);
        l_a = l_a * aa + sa;
        l_b = l_b * ab + sb;
        l_c = l_c * ac + sc;
        l_d = l_d * ad + sd;

#pragma unroll
        for (int nt = 0; nt < 16; nt++) {
            o[0][nt][0] *= aa; o[0][nt][1] *= aa;
            o[0][nt][2] *= ab; o[0][nt][3] *= ab;
            o[1][nt][0] *= ac; o[1][nt][1] *= ac;
            o[1][nt][2] *= ad; o[1][nt][3] *= ad;
        }

        // --- O += P V ---
#pragma unroll
        for (int kc = 0; kc < 4; kc++) {
#pragma unroll
            for (int ntp = 0; ntp < 8; ntp++) {
                uint32_t bf0[2], bf1[2];
                ldsm4t(bf0[0], bf0[1], bf1[0], bf1[1],
                       Vb + (kc * 16 + arow) * QP + ntp * 16 + acol);
                mma_f16(o[0][2 * ntp], aP[0][kc], bf0);
                mma_f16(o[0][2 * ntp + 1], aP[0][kc], bf1);
                mma_f16(o[1][2 * ntp], aP[1][kc], bf0);
                mma_f16(o[1][2 * ntp + 1], aP[1][kc], bf1);
            }
        }
    }

    // --- epilogue ---
    float ia = 1.f / l_a, ib = 1.f / l_b, ic = 1.f / l_c, id = 1.f / l_d;
    half* Op = O + headOff + (size_t)(qt * 128) * DD;
#pragma unroll
    for (int nt = 0; nt < 16; nt++) {
        int cc = nt * 8 + 2 * c4;
        *(half2*)(Op + (size_t)qa * DD + cc) =
            __floats2half2_rn(o[0][nt][0] * ia, o[0][nt][1] * ia);
        *(half2*)(Op + (size_t)qb * DD + cc) =
            __floats2half2_rn(o[0][nt][2] * ib, o[0][nt][3] * ib);
        *(half2*)(Op + (size_t)qc * DD + cc) =
            __floats2half2_rn(o[1][nt][0] * ic, o[1][nt][1] * ic);
        *(half2*)(Op + (size_t)qd * DD + cc) =
            __floats2half2_rn(o[1][nt][2] * id, o[1][nt][3] * id);
    }
}

// ---------------------------------------------------------------------------
extern "C" void kernel_launch(void* const* d_in, const int* in_sizes, int n_in,
                              void* d_out, int out_size)
{
    const float* x  = (const float*)d_in[0];
    const float* Wq = (const float*)d_in[1];
    const float* Wk = (const float*)d_in[2];
    const float* Wv = (const float*)d_in[3];
    const float* Wo = (const float*)d_in[4];
    float* out = (float*)d_out;

    half *xh, *wqh, *wkh, *wvh, *woh, *q, *k, *v, *a;
    cudaGetSymbolAddress((void**)&xh,  g_xh);
    cudaGetSymbolAddress((void**)&wqh, g_wqh);
    cudaGetSymbolAddress((void**)&wkh, g_wkh);
    cudaGetSymbolAddress((void**)&wvh, g_wvh);
    cudaGetSymbolAddress((void**)&woh, g_woh);
    cudaGetSymbolAddress((void**)&q, g_q);
    cudaGetSymbolAddress((void**)&k, g_k);
    cudaGetSymbolAddress((void**)&v, g_v);
    cudaGetSymbolAddress((void**)&a, g_a);

    // 1/sqrt(128) * log2(e): softmax in base-2 domain
    const float scale = 0.08838834764831845f * 1.4426950408889634f;

    conv_all<<<dim3(1024, 5), 256>>>(x, Wq, Wk, Wv, Wo,
                                     xh, wqh, wkh, wvh, woh, scale);

    const int gemm_smem = 3 * GSTG * 2;  // 107520
    cudaFuncSetAttribute(gemm_f16<true>,
                         cudaFuncAttributeMaxDynamicSharedMemorySize, gemm_smem);
    cudaFuncSetAttribute(gemm_f16<false>,
                         cudaFuncAttributeMaxDynamicSharedMemorySize, gemm_smem);
    const int attn_smem = (128 * QP + 4 * KVSZ) * 2;  // 104448
    cudaFuncSetAttribute(attn_f16,
                         cudaFuncAttributeMaxDynamicSharedMemorySize, attn_smem);

    // fused QKV projection (half out)
    gemm_f16<true><<<dim3(DD / 128, MTOT / 128, 3), 128, gemm_smem>>>(
        xh, wqh, wkh, wvh, q, k, v, MTOT, DD, DD);

    attn_f16<<<dim3(NN / 128, BB * 8), 128, attn_smem>>>(q, k, v, a);

    // output projection (float out)
    gemm_f16<false><<<dim3(DD / 128, MTOT / 128, 1), 128, gemm_smem>>>(
        a, woh, woh, woh, out, out, out, MTOT, DD, DD);
}

// round 17
// speedup vs baseline: 1.0361x; 1.0361x over previous
#include <cuda_runtime.h>
#include <cuda_fp16.h>
#include <cstdint>

#define BB 4
#define NN 2048
#define DD 1024
#define MTOT (BB * NN)  // 8192

// fp16 scratch (allocation-free rule: __device__ globals)
static __device__ __align__(256) half g_xh[MTOT * DD];
static __device__ __align__(256) half g_wqh[DD * DD];
static __device__ __align__(256) half g_wkh[DD * DD];
static __device__ __align__(256) half g_wvh[DD * DD];
static __device__ __align__(256) half g_woh[DD * DD];
static __device__ __align__(256) half g_q[MTOT * DD];
static __device__ __align__(256) half g_k[MTOT * DD];
static __device__ __align__(256) half g_v[MTOT * DD];
static __device__ __align__(256) half g_a[MTOT * DD];

// ---------------------------------------------------------------------------
__device__ __forceinline__ uint32_t h2u(half2 h) {
    return *reinterpret_cast<uint32_t*>(&h);
}

__device__ __forceinline__ float ex2(float x) {
    float r;
    asm("ex2.approx.f32 %0, %1;" : "=f"(r) : "f"(x));
    return r;
}

__device__ __forceinline__ void mma_f16(float d[4], const uint32_t a[4],
                                        const uint32_t b[2]) {
    asm volatile(
        "mma.sync.aligned.m16n8k16.row.col.f32.f16.f16.f32 "
        "{%0,%1,%2,%3}, {%4,%5,%6,%7}, {%8,%9}, {%0,%1,%2,%3};"
        : "+f"(d[0]), "+f"(d[1]), "+f"(d[2]), "+f"(d[3])
        : "r"(a[0]), "r"(a[1]), "r"(a[2]), "r"(a[3]), "r"(b[0]), "r"(b[1]));
}

__device__ __forceinline__ void ldsm4(uint32_t& m0, uint32_t& m1, uint32_t& m2,
                                      uint32_t& m3, const half* p) {
    uint32_t sa = (uint32_t)__cvta_generic_to_shared(p);
    asm volatile(
        "ldmatrix.sync.aligned.m8n8.x4.shared.b16 {%0,%1,%2,%3}, [%4];"
        : "=r"(m0), "=r"(m1), "=r"(m2), "=r"(m3) : "r"(sa));
}

__device__ __forceinline__ void ldsm4t(uint32_t& m0, uint32_t& m1, uint32_t& m2,
                                       uint32_t& m3, const half* p) {
    uint32_t sa = (uint32_t)__cvta_generic_to_shared(p);
    asm volatile(
        "ldmatrix.sync.aligned.m8n8.x4.trans.shared.b16 {%0,%1,%2,%3}, [%4];"
        : "=r"(m0), "=r"(m1), "=r"(m2), "=r"(m3) : "r"(sa));
}

__device__ __forceinline__ void cp16(void* smem, const void* g) {
    uint32_t s = (uint32_t)__cvta_generic_to_shared(smem);
    asm volatile("cp.async.ca.shared.global [%0], [%1], 16;" :: "r"(s), "l"(g));
}

// ---------------------------------------------------------------------------
// fused convert: y=0 -> x (scale 1), y=1..4 -> Wq(qscale)/Wk/Wv/Wo
// ---------------------------------------------------------------------------
__global__ void conv_all(const float* __restrict__ x,
                         const float* __restrict__ Wq,
                         const float* __restrict__ Wk,
                         const float* __restrict__ Wv,
                         const float* __restrict__ Wo,
                         half* ox, half* oq, half* ok, half* ov, half* oo,
                         float qscale)
{
    const int ysel = blockIdx.y;
    const float* in = (ysel == 0) ? x : (ysel == 1) ? Wq : (ysel == 2) ? Wk
                                      : (ysel == 3) ? Wv : Wo;
    half* out = (ysel == 0) ? ox : (ysel == 1) ? oq : (ysel == 2) ? ok
                                 : (ysel == 3) ? ov : oo;
    const float s = (ysel == 1) ? qscale : 1.0f;
    const int n4 = (ysel == 0) ? (MTOT * DD / 4) : (DD * DD / 4);
    const int stride = gridDim.x * blockDim.x;
    int i = blockIdx.x * blockDim.x + threadIdx.x;
    for (; i + 3 * stride < n4; i += 4 * stride) {
        float4 f0 = ((const float4*)in)[i];
        float4 f1 = ((const float4*)in)[i + stride];
        float4 f2 = ((const float4*)in)[i + 2 * stride];
        float4 f3 = ((const float4*)in)[i + 3 * stride];
        ((half2*)out)[2 * i]     = __floats2half2_rn(f0.x * s, f0.y * s);
        ((half2*)out)[2 * i + 1] = __floats2half2_rn(f0.z * s, f0.w * s);
        ((half2*)out)[2 * (i + stride)]     = __floats2half2_rn(f1.x * s, f1.y * s);
        ((half2*)out)[2 * (i + stride) + 1] = __floats2half2_rn(f1.z * s, f1.w * s);
        ((half2*)out)[2 * (i + 2 * stride)]     = __floats2half2_rn(f2.x * s, f2.y * s);
        ((half2*)out)[2 * (i + 2 * stride) + 1] = __floats2half2_rn(f2.z * s, f2.w * s);
        ((half2*)out)[2 * (i + 3 * stride)]     = __floats2half2_rn(f3.x * s, f3.y * s);
        ((half2*)out)[2 * (i + 3 * stride) + 1] = __floats2half2_rn(f3.z * s, f3.w * s);
    }
    for (; i < n4; i += stride) {
        float4 f = ((const float4*)in)[i];
        ((half2*)out)[2 * i]     = __floats2half2_rn(f.x * s, f.y * s);
        ((half2*)out)[2 * i + 1] = __floats2half2_rn(f.z * s, f.w * s);
    }
}

// ---------------------------------------------------------------------------
// fp16 GEMM (R14 body, PERSISTENT): block tile 128x128, BK=32, 128 threads
// (4 warps, 2m x 2n, warp tile 64x64), 3-stage cp.async, one barrier/chunk.
// Persistent: grid = 2*SMs CTAs loop over all (z, y, x) tiles -> no wave tail.
// smem: 3*(128*40 + 32*136)*2 = 56832 B -> 2 blocks/SM.
// ---------------------------------------------------------------------------
#define GAH 40
#define GBH 136
#define GSTG (128 * GAH + 32 * GBH)   // halves per stage

template <bool HOUT>
__global__ __launch_bounds__(128, 2) void gemm_f16(
    const half* __restrict__ A,
    const half* __restrict__ W0, const half* __restrict__ W1,
    const half* __restrict__ W2,
    void* __restrict__ C0, void* __restrict__ C1, void* __restrict__ C2,
    int M, int N, int K, int nTx, int nTy, int nTz)
{
    extern __shared__ half gsm[];

    const int tid = threadIdx.x;
    const int lane = tid & 31;
    const int wid = tid >> 5;          // 0..3
    const int wm = (wid & 1) * 64;
    const int wn = (wid >> 1) * 64;
    const int g  = lane >> 2;
    const int c4 = lane & 3;

    const int arow = (lane & 7) + ((lane >> 3) & 1) * 8;
    const int acol = (lane >> 4) * 8;

    const int nTiles = nTx * nTy * nTz;

    for (int tile = blockIdx.x; tile < nTiles; tile += gridDim.x) {
        const int tx = tile % nTx;
        const int ty = (tile / nTx) % nTy;
        const int tz = tile / (nTx * nTy);
        const half* Bm = (tz == 0) ? W0 : (tz == 1) ? W1 : W2;
        void* Cv = (tz == 0) ? C0 : (tz == 1) ? C1 : C2;
        const int rowBase = ty * 128;
        const int colBase = tx * 128;

        float acc[4][8][4] = {};

        auto load_stage = [&](int kt, int stg) {
            half* Asb = gsm + stg * GSTG;
            half* Bsb = Asb + 128 * GAH;
#pragma unroll
            for (int j = 0; j < 4; j++) {
                int ch = tid + 128 * j;        // 512 chunks of 8 halves (A)
                int r = ch >> 2, c = (ch & 3) * 8;
                cp16(&Asb[r * GAH + c], A + (size_t)(rowBase + r) * K + kt + c);
            }
#pragma unroll
            for (int j = 0; j < 4; j++) {
                int ch = tid + 128 * j;        // 512 chunks of 8 halves (B)
                int kr = ch >> 4, c = (ch & 15) * 8;
                cp16(&Bsb[kr * GBH + c],
                     Bm + (size_t)(kt + kr) * N + colBase + c);
            }
            asm volatile("cp.async.commit_group;" ::: "memory");
        };

        load_stage(0, 0);
        load_stage(32, 1);

        const int T = K / 32;
        for (int t = 0; t < T; t++) {
            if (t + 1 < T)
                asm volatile("cp.async.wait_group 1;" ::: "memory");
            else
                asm volatile("cp.async.wait_group 0;" ::: "memory");
            __syncthreads();   // stage t ready; all warps done with stage t-1

            int stg = t % 3;
            const half* Asb = gsm + stg * GSTG;
            const half* Bsb = Asb + 128 * GAH;

#pragma unroll
            for (int ks = 0; ks < 2; ks++) {
                uint32_t a[4][4], b[8][2];
#pragma unroll
                for (int mt = 0; mt < 4; mt++)
                    ldsm4(a[mt][0], a[mt][1], a[mt][2], a[mt][3],
                          Asb + (wm + mt * 16 + arow) * GAH + ks * 16 + acol);
#pragma unroll
                for (int ntp = 0; ntp < 4; ntp++)
                    ldsm4t(b[2 * ntp][0], b[2 * ntp][1],
                           b[2 * ntp + 1][0], b[2 * ntp + 1][1],
                           Bsb + (ks * 16 + arow) * GBH + wn + ntp * 16 + acol);
#pragma unroll
                for (int mt = 0; mt < 4; mt++)
#pragma unroll
                    for (int nt = 0; nt < 8; nt++)
                        mma_f16(acc[mt][nt], a[mt], b[nt]);
            }

            if (t + 2 < T)
                load_stage((t + 2) * 32, (t + 2) % 3);
        }

#pragma unroll
        for (int mt = 0; mt < 4; mt++) {
            int r0 = rowBase + wm + mt * 16 + g;
#pragma unroll
            for (int nt = 0; nt < 8; nt++) {
                int cc = colBase + wn + nt * 8 + 2 * c4;
                if (HOUT) {
                    half* C = (half*)Cv;
                    *(half2*)(C + (size_t)r0 * N + cc) =
                        __floats2half2_rn(acc[mt][nt][0], acc[mt][nt][1]);
                    *(half2*)(C + (size_t)(r0 + 8) * N + cc) =
                        __floats2half2_rn(acc[mt][nt][2], acc[mt][nt][3]);
                } else {
                    float* C = (float*)Cv;
                    *(float2*)(C + (size_t)r0 * N + cc) =
                        make_float2(acc[mt][nt][0], acc[mt][nt][1]);
                    *(float2*)(C + (size_t)(r0 + 8) * N + cc) =
                        make_float2(acc[mt][nt][2], acc[mt][nt][3]);
                }
            }
        }
        __syncthreads();   // epilogue smem-read-free but keep tiles separated
    }
}

// ---------------------------------------------------------------------------
// fp16 flash attention (R14 body, PERSISTENT + alpha==1 rescale skip).
// 128 threads, 4 warps x 32 q-rows, 2 blocks/SM, base-2 softmax.
// Persistent: grid = 2*SMs CTAs loop over the 512 (qt, bh) tiles.
// ---------------------------------------------------------------------------
#define QP 136
#define KVSZ (64 * QP)
#define NQT (NN / 128)   // 16

__global__ __launch_bounds__(128, 2) void attn_f16(
    const half* __restrict__ Q, const half* __restrict__ K,
    const half* __restrict__ V, half* __restrict__ O)
{
    extern __shared__ half smh[];
    half* Qs = smh;                    // 128*136
    half* Ks = Qs + 128 * QP;          // [2][64*136]
    half* Vs = Ks + 2 * KVSZ;          // [2][64*136]

    const int tid = threadIdx.x;
    const int lane = tid & 31;
    const int wid = tid >> 5;          // 0..3 -> q rows 32*wid..
    const int g  = lane >> 2;
    const int c4 = lane & 3;

    const int rb0 = wid * 32;
    const int rb1 = wid * 32 + 16;
    const int qa = rb0 + g;
    const int qb = qa + 8;
    const int qc = rb1 + g;
    const int qd = qc + 8;

    const int arow = (lane & 7) + ((lane >> 3) & 1) * 8;
    const int acol = (lane >> 4) * 8;
    const int brow = (lane & 7) + ((lane >> 4) & 1) * 8;
    const int bcol = ((lane >> 3) & 1) * 8;

    const int nTiles = NQT * BB * 8;   // 512

    for (int tile = blockIdx.x; tile < nTiles; tile += gridDim.x) {
        const int qt = tile % NQT;
        const int bh = tile / NQT;
        const int b = bh >> 3;
        const int h = bh & 7;

        const size_t headOff = (size_t)b * NN * DD + (size_t)h * 128;
        const half* Qp = Q + headOff + (size_t)(qt * 128) * DD;
        const half* Kp = K + headOff;
        const half* Vp = V + headOff;

        auto load_kv = [&](int kt, int bufi) {
#pragma unroll
            for (int j = 0; j < 8; j++) {
                int ch = tid + 128 * j;
                int r = ch >> 4, c = (ch & 15) * 8;
                const size_t go = (size_t)(kt * 64 + r) * DD + c;
                cp16(&Ks[bufi * KVSZ + r * QP + c], Kp + go);
                cp16(&Vs[bufi * KVSZ + r * QP + c], Vp + go);
            }
        };

#pragma unroll
        for (int j = 0; j < 16; j++) {
            int ch = tid + 128 * j;
            int r = ch >> 4, c = (ch & 15) * 8;
            cp16(&Qs[r * QP + c], Qp + (size_t)r * DD + c);
        }
        load_kv(0, 0);
        asm volatile("cp.async.commit_group;" ::: "memory");

        float o[2][16][4] = {};
        float m_a = -1e30f, m_b = -1e30f, m_c = -1e30f, m_d = -1e30f;
        float l_a = 0.f, l_b = 0.f, l_c = 0.f, l_d = 0.f;

        for (int kt = 0; kt < 32; kt++) {
            asm volatile("cp.async.wait_group 0;" ::: "memory");
            __syncthreads();
            if (kt + 1 < 32) {
                load_kv(kt + 1, (kt + 1) & 1);
                asm volatile("cp.async.commit_group;" ::: "memory");
            }
            const half* Kb = Ks + (kt & 1) * KVSZ;
            const half* Vb = Vs + (kt & 1) * KVSZ;

            // --- S = Q K^T (base-2 logits) ---
            float s[2][8][4] = {};
#pragma unroll
            for (int ks = 0; ks < 8; ks++) {
                uint32_t a0[4], a1[4];
                ldsm4(a0[0], a0[1], a0[2], a0[3],
                      Qs + (rb0 + arow) * QP + ks * 16 + acol);
                ldsm4(a1[0], a1[1], a1[2], a1[3],
                      Qs + (rb1 + arow) * QP + ks * 16 + acol);
#pragma unroll
                for (int ntp = 0; ntp < 4; ntp++) {
                    uint32_t bf0[2], bf1[2];
                    ldsm4(bf0[0], bf0[1], bf1[0], bf1[1],
                          Kb + (ntp * 16 + brow) * QP + ks * 16 + bcol);
                    mma_f16(s[0][2 * ntp], a0, bf0);
                    mma_f16(s[0][2 * ntp + 1], a0, bf1);
                    mma_f16(s[1][2 * ntp], a1, bf0);
                    mma_f16(s[1][2 * ntp + 1], a1, bf1);
                }
            }

            // --- warp-local softmax (base 2) ---
            float pa = -1e30f, pb = -1e30f, pc = -1e30f, pd = -1e30f;
#pragma unroll
            for (int nt = 0; nt < 8; nt++) {
                pa = fmaxf(pa, fmaxf(s[0][nt][0], s[0][nt][1]));
                pb = fmaxf(pb, fmaxf(s[0][nt][2], s[0][nt][3]));
                pc = fmaxf(pc, fmaxf(s[1][nt][0], s[1][nt][1]));
                pd = fmaxf(pd, fmaxf(s[1][nt][2], s[1][nt][3]));
            }
            pa = fmaxf(pa, __shfl_xor_sync(0xffffffffu, pa, 1));
            pa = fmaxf(pa, __shfl_xor_sync(0xffffffffu, pa, 2));
            pb = fmaxf(pb, __shfl_xor_sync(0xffffffffu, pb, 1));
            pb = fmaxf(pb, __shfl_xor_sync(0xffffffffu, pb, 2));
            pc = fmaxf(pc, __shfl_xor_sync(0xffffffffu, pc, 1));
            pc = fmaxf(pc, __shfl_xor_sync(0xffffffffu, pc, 2));
            pd = fmaxf(pd, __shfl_xor_sync(0xffffffffu, pd, 1));
            pd = fmaxf(pd, __shfl_xor_sync(0xffffffffu, pd, 2));
            float na = fmaxf(m_a, pa), nb = fmaxf(m_b, pb);
            float nc = fmaxf(m_c, pc), nd = fmaxf(m_d, pd);
            float aa = ex2(m_a - na), ab = ex2(m_b - nb);
            float ac = ex2(m_c - nc), ad = ex2(m_d - nd);
            m_a = na; m_b = nb; m_c = nc; m_d = nd;

            uint32_t aP[2][4][4];
            float sa = 0.f, sb = 0.f, sc = 0.f, sd = 0.f;
#pragma unroll
            for (int nt = 0; nt < 8; nt++) {
                int kc = nt >> 1;
                int sl = (nt & 1) * 2;
                {
                    float p0 = ex2(s[0][nt][0] - na);
                    float p1 = ex2(s[0][nt][1] - na);
                    float p2 = ex2(s[0][nt][2] - nb);
                    float p3 = ex2(s[0][nt][3] - nb);
                    sa += p0 + p1;
                    sb += p2 + p3;
                    aP[0][kc][sl]     = h2u(__floats2half2_rn(p0, p1));
                    aP[0][kc][sl + 1] = h2u(__floats2half2_rn(p2, p3));
                }
                {
                    float p0 = ex2(s[1][nt][0] - nc);
                    float p1 = ex2(s[1][nt][1] - nc);
                    float p2 = ex2(s[1][nt][2] - nd);
                    float p3 = ex2(s[1][nt][3] - nd);
                    sc += p0 + p1;
                    sd += p2 + p3;
                    aP[1][kc][sl]     = h2u(__floats2half2_rn(p0, p1));
                    aP[1][kc][sl + 1] = h2u(__floats2half2_rn(p2, p3));
                }
            }
            sa += __shfl_xor_sync(0xffffffffu, sa, 1);
            sa += __shfl_xor_sync(0xffffffffu, sa, 2);
            sb += __shfl_xor_sync(0xffffffffu, sb, 1);
            sb += __shfl_xor_sync(0xffffffffu, sb, 2);
            sc += __shfl_xor_sync(0xffffffffu, sc, 1);
            sc += __shfl_xor_sync(0xffffffffu, sc, 2);
            sd += __shfl_xor_sync(0xffffffffu, sd, 1);
            sd += __shfl_xor_sync(0xffffffffu, sd, 2);
            l_a = l_a * aa + sa;
            l_b = l_b * ab + sb;
            l_c = l_c * ac + sc;
            l_d = l_d * ad + sd;

            // rescale O only when a max actually moved (ex2(0) == 1 exactly)
            if (!(aa == 1.f && ab == 1.f)) {
#pragma unroll
                for (int nt = 0; nt < 16; nt++) {
                    o[0][nt][0] *= aa; o[0][nt][1] *= aa;
                    o[0][nt][2] *= ab; o[0][nt][3] *= ab;
                }
            }
            if (!(ac == 1.f && ad == 1.f)) {
#pragma unroll
                for (int nt = 0; nt < 16; nt++) {
                    o[1][nt][0] *= ac; o[1][nt][1] *= ac;
                    o[1][nt][2] *= ad; o[1][nt][3] *= ad;
                }
            }

            // --- O += P V ---
#pragma unroll
            for (int kc = 0; kc < 4; kc++) {
#pragma unroll
                for (int ntp = 0; ntp < 8; ntp++) {
                    uint32_t bf0[2], bf1[2];
                    ldsm4t(bf0[0], bf0[1], bf1[0], bf1[1],
                           Vb + (kc * 16 + arow) * QP + ntp * 16 + acol);
                    mma_f16(o[0][2 * ntp], aP[0][kc], bf0);
                    mma_f16(o[0][2 * ntp + 1], aP[0][kc], bf1);
                    mma_f16(o[1][2 * ntp], aP[1][kc], bf0);
                    mma_f16(o[1][2 * ntp + 1], aP[1][kc], bf1);
                }
            }
        }

        // --- epilogue ---
        float ia = 1.f / l_a, ib = 1.f / l_b, ic = 1.f / l_c, id = 1.f / l_d;
        half* Op = O + headOff + (size_t)(qt * 128) * DD;
#pragma unroll
        for (int nt = 0; nt < 16; nt++) {
            int cc = nt * 8 + 2 * c4;
            *(half2*)(Op + (size_t)qa * DD + cc) =
                __floats2half2_rn(o[0][nt][0] * ia, o[0][nt][1] * ia);
            *(half2*)(Op + (size_t)qb * DD + cc) =
                __floats2half2_rn(o[0][nt][2] * ib, o[0][nt][3] * ib);
            *(half2*)(Op + (size_t)qc * DD + cc) =
                __floats2half2_rn(o[1][nt][0] * ic, o[1][nt][1] * ic);
            *(half2*)(Op + (size_t)qd * DD + cc) =
                __floats2half2_rn(o[1][nt][2] * id, o[1][nt][3] * id);
        }
        __syncthreads();   // tile state clean before next tile's smem loads
    }
}

// ---------------------------------------------------------------------------
extern "C" void kernel_launch(void* const* d_in, const int* in_sizes, int n_in,
                              void* d_out, int out_size)
{
    const float* x  = (const float*)d_in[0];
    const float* Wq = (const float*)d_in[1];
    const float* Wk = (const float*)d_in[2];
    const float* Wv = (const float*)d_in[3];
    const float* Wo = (const float*)d_in[4];
    float* out = (float*)d_out;

    half *xh, *wqh, *wkh, *wvh, *woh, *q, *k, *v, *a;
    cudaGetSymbolAddress((void**)&xh,  g_xh);
    cudaGetSymbolAddress((void**)&wqh, g_wqh);
    cudaGetSymbolAddress((void**)&wkh, g_wkh);
    cudaGetSymbolAddress((void**)&wvh, g_wvh);
    cudaGetSymbolAddress((void**)&woh, g_woh);
    cudaGetSymbolAddress((void**)&q, g_q);
    cudaGetSymbolAddress((void**)&k, g_k);
    cudaGetSymbolAddress((void**)&v, g_v);
    cudaGetSymbolAddress((void**)&a, g_a);

    int smCount = 148;
    cudaDeviceGetAttribute(&smCount, cudaDevAttrMultiProcessorCount, 0);
    const int pgrid = 2 * smCount;   // 2 blocks/SM, persistent

    // 1/sqrt(128) * log2(e): softmax in base-2 domain
    const float scale = 0.08838834764831845f * 1.4426950408889634f;

    conv_all<<<dim3(1024, 5), 256>>>(x, Wq, Wk, Wv, Wo,
                                     xh, wqh, wkh, wvh, woh, scale);

    const int gemm_smem = 3 * GSTG * 2;  // 56832
    cudaFuncSetAttribute(gemm_f16<true>,
                         cudaFuncAttributeMaxDynamicSharedMemorySize, gemm_smem);
    cudaFuncSetAttribute(gemm_f16<false>,
                         cudaFuncAttributeMaxDynamicSharedMemorySize, gemm_smem);
    const int attn_smem = (128 * QP + 4 * KVSZ) * 2;  // 104448
    cudaFuncSetAttribute(attn_f16,
                         cudaFuncAttributeMaxDynamicSharedMemorySize, attn_smem);

    // fused QKV projection (half out), persistent
    gemm_f16<true><<<pgrid, 128, gemm_smem>>>(
        xh, wqh, wkh, wvh, q, k, v, MTOT, DD, DD, DD / 128, MTOT / 128, 3);

    // attention, persistent
    attn_f16<<<pgrid, 128, attn_smem>>>(q, k, v, a);

    // output projection (float out), persistent
    gemm_f16<false><<<pgrid, 128, gemm_smem>>>(
        a, woh, woh, woh, out, out, out, MTOT, DD, DD, DD / 128, MTOT / 128, 1);
}